// round 4
// baseline (speedup 1.0000x reference)
#include <cuda_runtime.h>
#include <cuda_bf16.h>
#include <math.h>
#include <stdint.h>

// ---------------------------------------------------------------------------
// Problem constants
// ---------------------------------------------------------------------------
#define BB    2
#define SSEQ  1024
#define DDIM  1024
#define HHH   16
#define DKV   64
#define DHH   4096
#define LLAY  8
#define VVOC  256
#define MM    (BB*SSEQ)        // 2048
#define NQKV  3072

// ---------------------------------------------------------------------------
// Scratch (device globals: allocation-free)
// ---------------------------------------------------------------------------
__device__ float g_x  [MM*DDIM];
__device__ float g_h  [MM*DDIM];
__device__ float g_qkv[MM*NQKV];

__device__ __nv_bfloat16 g_xhi[MM*DDIM], g_xlo[MM*DDIM];
__device__ __nv_bfloat16 g_ohi[MM*DDIM], g_olo[MM*DDIM];
__device__ __nv_bfloat16 g_hhi[MM*DDIM], g_hlo[MM*DDIM];
__device__ __nv_bfloat16 g_thi[MM*DHH], g_tlo[MM*DHH];

__device__ __nv_bfloat16 g_Wqkv_hi[LLAY*NQKV*DDIM], g_Wqkv_lo[LLAY*NQKV*DDIM];
__device__ __nv_bfloat16 g_Wo_hi  [LLAY*DDIM*DDIM], g_Wo_lo  [LLAY*DDIM*DDIM];
__device__ __nv_bfloat16 g_W1_hi  [LLAY*DHH*DDIM],  g_W1_lo  [LLAY*DHH*DDIM];
__device__ __nv_bfloat16 g_W2_hi  [LLAY*DDIM*DHH],  g_W2_lo  [LLAY*DDIM*DHH];
__device__ __nv_bfloat16 g_Wr_hi  [VVOC*DDIM],      g_Wr_lo  [VVOC*DDIM];
__device__ float g_bqkv[LLAY*NQKV];

// ---------------------------------------------------------------------------
// Helpers
// ---------------------------------------------------------------------------
__device__ __forceinline__ uint32_t smem_u32(const void* p) {
    uint32_t a;
    asm("{ .reg .u64 t; cvta.to.shared.u64 t, %1; cvt.u32.u64 %0, t; }"
        : "=r"(a) : "l"(p));
    return a;
}

__device__ __forceinline__ void ldmx4(uint32_t* r, uint32_t addr) {
    asm volatile("ldmatrix.sync.aligned.m8n8.x4.shared.b16 {%0,%1,%2,%3}, [%4];"
        : "=r"(r[0]), "=r"(r[1]), "=r"(r[2]), "=r"(r[3]) : "r"(addr));
}

__device__ __forceinline__ void mma16816(float* d, const uint32_t* a,
                                         uint32_t b0, uint32_t b1) {
    asm volatile("mma.sync.aligned.m16n8k16.row.col.f32.bf16.bf16.f32 "
        "{%0,%1,%2,%3}, {%4,%5,%6,%7}, {%8,%9}, {%0,%1,%2,%3};"
        : "+f"(d[0]), "+f"(d[1]), "+f"(d[2]), "+f"(d[3])
        : "r"(a[0]), "r"(a[1]), "r"(a[2]), "r"(a[3]), "r"(b0), "r"(b1));
}

__device__ __forceinline__ void cp16(uint32_t dst, const void* src) {
    asm volatile("cp.async.cg.shared.global [%0], [%1], 16;"
        :: "r"(dst), "l"(src) : "memory");
}
#define CP_COMMIT() asm volatile("cp.async.commit_group;" ::: "memory")
#define CP_WAIT1()  asm volatile("cp.async.wait_group 1;"  ::: "memory")

__device__ __forceinline__ float gelu_exact(float v) {
    return 0.5f * v * (1.0f + erff(v * 0.70710678118654752f));
}

// split val -> hi (bf16 rn) + lo (bf16 rn of remainder)
__device__ __forceinline__ void split1(float v, __nv_bfloat16& hi, __nv_bfloat16& lo) {
    hi = __float2bfloat16(v);
    lo = __float2bfloat16(v - __bfloat162float(hi));
}

// ---------------------------------------------------------------------------
// GEMM: C = act(A @ Bt^T + bias) + res
// A given as (Ahi,Alo) bf16 [M,K]; Bt as (Bhi,Blo) bf16 [N,K].
// D = Ahi*Bhi + Ahi*Blo + Alo*Bhi  (fp32 accum)
// 128x128 tile, BK=32, 8 warps (2x4), 3-stage cp.async pipeline.
// Epilogue writes optional fp32 C and optional bf16 hi/lo split of C.
// ---------------------------------------------------------------------------
#define LDB     80
#define TILE_B  (128*LDB)          // 10240
#define OFF_AHI 0
#define OFF_ALO (1*TILE_B)
#define OFF_BHI (2*TILE_B)
#define OFF_BLO (3*TILE_B)
#define STAGE_B (4*TILE_B)         // 40960
#define NST     3
#define GSMEM   (NST*STAGE_B)      // 122880

__global__ void __launch_bounds__(256)
gemm_pair(const __nv_bfloat16* __restrict__ Ahi, const __nv_bfloat16* __restrict__ Alo,
          const __nv_bfloat16* __restrict__ Bhi, const __nv_bfloat16* __restrict__ Blo,
          const float* __restrict__ bias, const float* __restrict__ res,
          float* __restrict__ Cf,
          __nv_bfloat16* __restrict__ Chi, __nv_bfloat16* __restrict__ Clo,
          int M, int N, int K, int gelu)
{
    extern __shared__ char sm[];
    const uint32_t smb = smem_u32(sm);

    const int tid  = threadIdx.x;
    const int lane = tid & 31;
    const int wid  = tid >> 5;
    const int wr   = wid >> 2;          // 0..1
    const int wc   = wid & 3;           // 0..3
    const int m0   = blockIdx.y * 128;
    const int n0   = blockIdx.x * 128;

    // cp.async staging: thread -> row = tid>>2 (+p*64), 16B chunk = tid&3
    const int crow = tid >> 2;
    const int cch  = tid & 3;
    const __nv_bfloat16* aHiG = Ahi + (size_t)(m0 + crow) * K + cch * 8;
    const __nv_bfloat16* aLoG = Alo + (size_t)(m0 + crow) * K + cch * 8;
    const __nv_bfloat16* bHiG = Bhi + (size_t)(n0 + crow) * K + cch * 8;
    const __nv_bfloat16* bLoG = Blo + (size_t)(n0 + crow) * K + cch * 8;
    const uint32_t dstBase = smb + (uint32_t)(crow * LDB + cch * 16);

    const int nIt = K >> 5;

    auto issue = [&](int it) {
        const uint32_t sp = dstBase + (uint32_t)(it % NST) * STAGE_B;
        const int koff = it * 32;
#pragma unroll
        for (int p = 0; p < 2; p++) {
            const uint32_t d = sp + p * 64 * LDB;
            const size_t   g = (size_t)p * 64 * K + koff;
            cp16(d + OFF_AHI, aHiG + g);
            cp16(d + OFF_ALO, aLoG + g);
            cp16(d + OFF_BHI, bHiG + g);
            cp16(d + OFF_BLO, bLoG + g);
        }
        CP_COMMIT();
    };

    float acc[4][4][4];
#pragma unroll
    for (int i = 0; i < 4; i++)
#pragma unroll
        for (int j = 0; j < 4; j++)
#pragma unroll
            for (int q = 0; q < 4; q++) acc[i][j][q] = 0.0f;

    issue(0);
    issue(1);

    for (int it = 0; it < nIt; ++it) {
        CP_WAIT1();
        __syncthreads();
        if (it + 2 < nIt) issue(it + 2);

        const uint32_t stage = smb + (uint32_t)(it % NST) * STAGE_B;
        const uint32_t aHiB = stage + OFF_AHI
            + (uint32_t)((wr * 64 + (lane & 15)) * LDB + (lane >> 4) * 16);
        const uint32_t aLoB = aHiB + TILE_B;
        const uint32_t bHiB = stage + OFF_BHI + (uint32_t)((wc * 32 + lane) * LDB);
        const uint32_t bLoB = bHiB + TILE_B;

#pragma unroll
        for (int kc = 0; kc < 2; kc++) {
            uint32_t ahi[4][4], alo[4][4];
            uint32_t bh0[4], bh1[4], bl0[4], bl1[4];
#pragma unroll
            for (int mt = 0; mt < 4; mt++) {
                ldmx4(ahi[mt], aHiB + mt * 16 * LDB + kc * 32);
                ldmx4(alo[mt], aLoB + mt * 16 * LDB + kc * 32);
            }
            ldmx4(bh0, bHiB + kc * 32);
            ldmx4(bh1, bHiB + kc * 32 + 16);
            ldmx4(bl0, bLoB + kc * 32);
            ldmx4(bl1, bLoB + kc * 32 + 16);

#pragma unroll
            for (int mt = 0; mt < 4; mt++)
#pragma unroll
                for (int nt = 0; nt < 4; nt++) {
                    mma16816(acc[mt][nt], ahi[mt], bh0[nt], bh1[nt]);
                    mma16816(acc[mt][nt], ahi[mt], bl0[nt], bl1[nt]);
                    mma16816(acc[mt][nt], alo[mt], bh0[nt], bh1[nt]);
                }
        }
        __syncthreads();
    }

    // ---- epilogue ----
    const int er = m0 + wr * 64 + (lane >> 2);
    const int ec = n0 + wc * 32 + (lane & 3) * 2;
#pragma unroll
    for (int mt = 0; mt < 4; mt++) {
#pragma unroll
        for (int half = 0; half < 2; half++) {
            const int row = er + mt * 16 + half * 8;
            const size_t rb = (size_t)row * N;
            const float* rrow = res ? res + rb : nullptr;
#pragma unroll
            for (int nt = 0; nt < 4; nt++) {
                const int col = ec + nt * 8;
                float v0 = acc[mt][nt][half * 2 + 0];
                float v1 = acc[mt][nt][half * 2 + 1];
                if (bias) { v0 += bias[col]; v1 += bias[col + 1]; }
                if (gelu) { v0 = gelu_exact(v0); v1 = gelu_exact(v1); }
                if (rrow) { v0 += rrow[col]; v1 += rrow[col + 1]; }
                if (Cf) *(float2*)(Cf + rb + col) = make_float2(v0, v1);
                if (Chi) {
                    __nv_bfloat16 h0, l0, h1, l1;
                    split1(v0, h0, l0);
                    split1(v1, h1, l1);
                    __nv_bfloat162 hp = __nv_bfloat162(h0, h1);
                    __nv_bfloat162 lp = __nv_bfloat162(l0, l1);
                    *(__nv_bfloat162*)(Chi + rb + col) = hp;
                    *(__nv_bfloat162*)(Clo + rb + col) = lp;
                }
            }
        }
    }
}

// ---------------------------------------------------------------------------
// Transpose + split: src[K,N] fp32 -> dhi/dlo[N,K] bf16
// ---------------------------------------------------------------------------
__global__ void transpose_split(const float* __restrict__ src,
                                __nv_bfloat16* __restrict__ dhi,
                                __nv_bfloat16* __restrict__ dlo,
                                int K, int N)
{
    __shared__ float t[32][33];
    const int k0 = blockIdx.y * 32, n0 = blockIdx.x * 32;
    const int tx = threadIdx.x, ty = threadIdx.y;   // (32, 8)
#pragma unroll
    for (int i = 0; i < 32; i += 8)
        t[ty + i][tx] = src[(size_t)(k0 + ty + i) * N + n0 + tx];
    __syncthreads();
#pragma unroll
    for (int i = 0; i < 32; i += 8) {
        float v = t[tx][ty + i];
        __nv_bfloat16 hi, lo;
        split1(v, hi, lo);
        const size_t idx = (size_t)(n0 + ty + i) * K + k0 + tx;
        dhi[idx] = hi;
        dlo[idx] = lo;
    }
}

__global__ void bias_concat(const float* __restrict__ bq, const float* __restrict__ bk,
                            const float* __restrict__ bv, float* __restrict__ dst)
{
    int l = blockIdx.y;
    int i = blockIdx.x * 256 + threadIdx.x;
    dst[l*NQKV + i]        = bq[l*DDIM + i];
    dst[l*NQKV + 1024 + i] = bk[l*DDIM + i];
    dst[l*NQKV + 2048 + i] = bv[l*DDIM + i];
}

// ---------------------------------------------------------------------------
// Embedding: x fp32 + split
// ---------------------------------------------------------------------------
__global__ void embed_kernel(const int* __restrict__ tokens,
                             const float* __restrict__ emb,
                             const float* __restrict__ pos,
                             float* __restrict__ x,
                             __nv_bfloat16* __restrict__ xhi,
                             __nv_bfloat16* __restrict__ xlo)
{
    int i = blockIdx.x;
    int s = i & (SSEQ - 1);
    int t = tokens[i];
    int d = threadIdx.x;
    const float4* e4 = (const float4*)(emb + (size_t)t * DDIM);
    const float4* p4 = (const float4*)(pos + (size_t)s * DDIM);
    float4 a = e4[d], b = p4[d];
    float4 v = make_float4(a.x + b.x, a.y + b.y, a.z + b.z, a.w + b.w);
    ((float4*)(x + (size_t)i * DDIM))[d] = v;

    __nv_bfloat16 h0,l0,h1,l1,h2,l2,h3,l3;
    split1(v.x, h0, l0); split1(v.y, h1, l1);
    split1(v.z, h2, l2); split1(v.w, h3, l3);
    __nv_bfloat162 hp0(h0, h1), hp1(h2, h3), lp0(l0, l1), lp1(l2, l3);
    __nv_bfloat162* xh = (__nv_bfloat162*)(xhi + (size_t)i * DDIM + d * 4);
    __nv_bfloat162* xl = (__nv_bfloat162*)(xlo + (size_t)i * DDIM + d * 4);
    xh[0] = hp0; xh[1] = hp1;
    xl[0] = lp0; xl[1] = lp1;
}

// ---------------------------------------------------------------------------
// Flash attention (causal), qkv packed [M,3072]; writes o split (bf16 hi/lo)
// ---------------------------------------------------------------------------
#define APAD 65
__global__ void __launch_bounds__(256)
attention_kernel(const float* __restrict__ qkv,
                 __nv_bfloat16* __restrict__ ohi, __nv_bfloat16* __restrict__ olo)
{
    extern __shared__ float smf[];
    float* Qs = smf;
    float* Ks = Qs + 64 * APAD;
    float* Vs = Ks + 64 * APAD;
    float* Ps = Vs + 64 * APAD;

    const int tid = threadIdx.x;
    const int qb  = blockIdx.x;
    const int bh  = blockIdx.y;
    const int b   = bh >> 4;
    const int h   = bh & 15;
    const size_t rowbase = (size_t)b * SSEQ;
    const int qc = h * DKV, kc = 1024 + h * DKV, vc = 2048 + h * DKV;

    const int ty = tid >> 4;
    const int tx = tid & 15;
    const float scale = 0.125f;

    for (int it = tid; it < 64 * 16; it += 256) {
        int rr = it >> 4, c4 = (it & 15) * 4;
        float4 a = *(const float4*)(qkv + (rowbase + qb*64 + rr) * NQKV + qc + c4);
        Qs[rr*APAD + c4+0] = a.x; Qs[rr*APAD + c4+1] = a.y;
        Qs[rr*APAD + c4+2] = a.z; Qs[rr*APAD + c4+3] = a.w;
    }

    float m[4], l[4], acc[4][4];
#pragma unroll
    for (int i = 0; i < 4; i++) {
        m[i] = -INFINITY; l[i] = 0.0f;
#pragma unroll
        for (int j = 0; j < 4; j++) acc[i][j] = 0.0f;
    }
    __syncthreads();

    for (int jt = 0; jt <= qb; jt++) {
        for (int it = tid; it < 64 * 16; it += 256) {
            int rr = it >> 4, c4 = (it & 15) * 4;
            const size_t grow = (rowbase + jt*64 + rr) * NQKV;
            float4 a = *(const float4*)(qkv + grow + kc + c4);
            Ks[rr*APAD + c4+0] = a.x; Ks[rr*APAD + c4+1] = a.y;
            Ks[rr*APAD + c4+2] = a.z; Ks[rr*APAD + c4+3] = a.w;
            float4 c = *(const float4*)(qkv + grow + vc + c4);
            Vs[rr*APAD + c4+0] = c.x; Vs[rr*APAD + c4+1] = c.y;
            Vs[rr*APAD + c4+2] = c.z; Vs[rr*APAD + c4+3] = c.w;
        }
        __syncthreads();

        float s[4][4];
#pragma unroll
        for (int i = 0; i < 4; i++)
#pragma unroll
            for (int j = 0; j < 4; j++) s[i][j] = 0.0f;
#pragma unroll 8
        for (int kk = 0; kk < 64; kk++) {
            float qv[4], kv[4];
#pragma unroll
            for (int i = 0; i < 4; i++) qv[i] = Qs[(ty*4+i)*APAD + kk];
#pragma unroll
            for (int j = 0; j < 4; j++) kv[j] = Ks[(tx*4+j)*APAD + kk];
#pragma unroll
            for (int i = 0; i < 4; i++)
#pragma unroll
                for (int j = 0; j < 4; j++) s[i][j] += qv[i] * kv[j];
        }

#pragma unroll
        for (int i = 0; i < 4; i++) {
            int qrow = qb*64 + ty*4 + i;
#pragma unroll
            for (int j = 0; j < 4; j++) {
                int kcol = jt*64 + tx*4 + j;
                s[i][j] = (kcol > qrow) ? -INFINITY : s[i][j] * scale;
            }
        }

#pragma unroll
        for (int i = 0; i < 4; i++) {
            float rm = fmaxf(fmaxf(s[i][0], s[i][1]), fmaxf(s[i][2], s[i][3]));
#pragma unroll
            for (int off = 1; off < 16; off <<= 1)
                rm = fmaxf(rm, __shfl_xor_sync(0xffffffffu, rm, off));
            float mnew = fmaxf(m[i], rm);
            float corr = expf(m[i] - mnew);
            l[i] *= corr;
#pragma unroll
            for (int j = 0; j < 4; j++) acc[i][j] *= corr;
            float rs = 0.0f;
#pragma unroll
            for (int j = 0; j < 4; j++) {
                float p = expf(s[i][j] - mnew);
                s[i][j] = p; rs += p;
            }
#pragma unroll
            for (int off = 1; off < 16; off <<= 1)
                rs += __shfl_xor_sync(0xffffffffu, rs, off);
            l[i] += rs; m[i] = mnew;
        }

#pragma unroll
        for (int i = 0; i < 4; i++)
#pragma unroll
            for (int j = 0; j < 4; j++)
                Ps[(ty*4+i)*APAD + tx*4 + j] = s[i][j];
        __syncthreads();

#pragma unroll 8
        for (int kk = 0; kk < 64; kk++) {
            float pv[4], vv[4];
#pragma unroll
            for (int i = 0; i < 4; i++) pv[i] = Ps[(ty*4+i)*APAD + kk];
#pragma unroll
            for (int j = 0; j < 4; j++) vv[j] = Vs[kk*APAD + tx*4 + j];
#pragma unroll
            for (int i = 0; i < 4; i++)
#pragma unroll
                for (int j = 0; j < 4; j++) acc[i][j] += pv[i] * vv[j];
        }
        __syncthreads();
    }

#pragma unroll
    for (int i = 0; i < 4; i++) {
        float inv = 1.0f / l[i];
        const size_t grow = (rowbase + qb*64 + ty*4 + i) * DDIM + h*DKV + tx*4;
        float v0 = acc[i][0]*inv, v1 = acc[i][1]*inv;
        float v2 = acc[i][2]*inv, v3 = acc[i][3]*inv;
        __nv_bfloat16 h0,l0,h1,l1,h2,l2,h3,l3;
        split1(v0, h0, l0); split1(v1, h1, l1);
        split1(v2, h2, l2); split1(v3, h3, l3);
        __nv_bfloat162* oh = (__nv_bfloat162*)(ohi + grow);
        __nv_bfloat162* ol = (__nv_bfloat162*)(olo + grow);
        oh[0] = __nv_bfloat162(h0, h1); oh[1] = __nv_bfloat162(h2, h3);
        ol[0] = __nv_bfloat162(l0, l1); ol[1] = __nv_bfloat162(l2, l3);
    }
}

// ---------------------------------------------------------------------------
// Host
// ---------------------------------------------------------------------------
static inline void run_gemm(const __nv_bfloat16* Ahi, const __nv_bfloat16* Alo,
                            const __nv_bfloat16* Bhi, const __nv_bfloat16* Blo,
                            const float* bias, const float* res,
                            float* Cf, __nv_bfloat16* Chi, __nv_bfloat16* Clo,
                            int M, int N, int K, int gelu)
{
    dim3 grid(N / 128, M / 128);
    gemm_pair<<<grid, 256, GSMEM>>>(Ahi, Alo, Bhi, Blo, bias, res,
                                    Cf, Chi, Clo, M, N, K, gelu);
}

static inline void trs(const float* s, __nv_bfloat16* dhi, __nv_bfloat16* dlo,
                       int K, int N)
{
    transpose_split<<<dim3(N / 32, K / 32), dim3(32, 8)>>>(s, dhi, dlo, K, N);
}

extern "C" void kernel_launch(void* const* d_in, const int* in_sizes, int n_in,
                              void* d_out, int out_size)
{
    const int*   tokens = (const int*)  d_in[0];
    const float* emb    = (const float*)d_in[1];
    const float* pos    = (const float*)d_in[2];
    const float* Wq     = (const float*)d_in[3];
    const float* bq     = (const float*)d_in[4];
    const float* Wk     = (const float*)d_in[5];
    const float* bk     = (const float*)d_in[6];
    const float* Wv     = (const float*)d_in[7];
    const float* bv     = (const float*)d_in[8];
    const float* Wo     = (const float*)d_in[9];
    const float* W1     = (const float*)d_in[10];
    const float* b1     = (const float*)d_in[11];
    const float* W2     = (const float*)d_in[12];
    const float* b2     = (const float*)d_in[13];
    const float* Wr     = (const float*)d_in[14];
    const float* br     = (const float*)d_in[15];
    float*       out    = (float*)d_out;

    float *x, *h, *qkv, *bqkv;
    __nv_bfloat16 *xhi, *xlo, *ohi, *olo, *hhi, *hlo, *thi, *tlo;
    __nv_bfloat16 *Wqkv_hi, *Wqkv_lo, *Wo_hi, *Wo_lo, *W1_hi, *W1_lo;
    __nv_bfloat16 *W2_hi, *W2_lo, *Wr_hi, *Wr_lo;
    cudaGetSymbolAddress((void**)&x,   g_x);
    cudaGetSymbolAddress((void**)&h,   g_h);
    cudaGetSymbolAddress((void**)&qkv, g_qkv);
    cudaGetSymbolAddress((void**)&bqkv, g_bqkv);
    cudaGetSymbolAddress((void**)&xhi, g_xhi);  cudaGetSymbolAddress((void**)&xlo, g_xlo);
    cudaGetSymbolAddress((void**)&ohi, g_ohi);  cudaGetSymbolAddress((void**)&olo, g_olo);
    cudaGetSymbolAddress((void**)&hhi, g_hhi);  cudaGetSymbolAddress((void**)&hlo, g_hlo);
    cudaGetSymbolAddress((void**)&thi, g_thi);  cudaGetSymbolAddress((void**)&tlo, g_tlo);
    cudaGetSymbolAddress((void**)&Wqkv_hi, g_Wqkv_hi);
    cudaGetSymbolAddress((void**)&Wqkv_lo, g_Wqkv_lo);
    cudaGetSymbolAddress((void**)&Wo_hi, g_Wo_hi);
    cudaGetSymbolAddress((void**)&Wo_lo, g_Wo_lo);
    cudaGetSymbolAddress((void**)&W1_hi, g_W1_hi);
    cudaGetSymbolAddress((void**)&W1_lo, g_W1_lo);
    cudaGetSymbolAddress((void**)&W2_hi, g_W2_hi);
    cudaGetSymbolAddress((void**)&W2_lo, g_W2_lo);
    cudaGetSymbolAddress((void**)&Wr_hi, g_Wr_hi);
    cudaGetSymbolAddress((void**)&Wr_lo, g_Wr_lo);

    cudaFuncSetAttribute(gemm_pair,
                         cudaFuncAttributeMaxDynamicSharedMemorySize, GSMEM);
    const int ASMEM = 4 * 64 * APAD * (int)sizeof(float);
    cudaFuncSetAttribute(attention_kernel,
                         cudaFuncAttributeMaxDynamicSharedMemorySize, ASMEM);

    // weight prep (transpose + split), once per launch
    for (int l = 0; l < LLAY; l++) {
        size_t wo = (size_t)l * NQKV * DDIM;
        trs(Wq + (size_t)l*DDIM*DDIM, Wqkv_hi + wo,                Wqkv_lo + wo,                DDIM, DDIM);
        trs(Wk + (size_t)l*DDIM*DDIM, Wqkv_hi + wo + DDIM*DDIM,    Wqkv_lo + wo + DDIM*DDIM,    DDIM, DDIM);
        trs(Wv + (size_t)l*DDIM*DDIM, Wqkv_hi + wo + 2u*DDIM*DDIM, Wqkv_lo + wo + 2u*DDIM*DDIM, DDIM, DDIM);
        trs(Wo + (size_t)l*DDIM*DDIM, Wo_hi + (size_t)l*DDIM*DDIM, Wo_lo + (size_t)l*DDIM*DDIM, DDIM, DDIM);
        trs(W1 + (size_t)l*DDIM*DHH,  W1_hi + (size_t)l*DHH*DDIM,  W1_lo + (size_t)l*DHH*DDIM,  DDIM, DHH);
        trs(W2 + (size_t)l*DHH*DDIM,  W2_hi + (size_t)l*DDIM*DHH,  W2_lo + (size_t)l*DDIM*DHH,  DHH,  DDIM);
    }
    trs(Wr, Wr_hi, Wr_lo, DDIM, VVOC);
    bias_concat<<<dim3(4, LLAY), 256>>>(bq, bk, bv, bqkv);

    embed_kernel<<<MM, 256>>>(tokens, emb, pos, x, xhi, xlo);

    for (int l = 0; l < LLAY; l++) {
        const __nv_bfloat16* wqh = Wqkv_hi + (size_t)l*NQKV*DDIM;
        const __nv_bfloat16* wql = Wqkv_lo + (size_t)l*NQKV*DDIM;
        const __nv_bfloat16* woh = Wo_hi + (size_t)l*DDIM*DDIM;
        const __nv_bfloat16* wol = Wo_lo + (size_t)l*DDIM*DDIM;
        const __nv_bfloat16* w1h = W1_hi + (size_t)l*DHH*DDIM;
        const __nv_bfloat16* w1l = W1_lo + (size_t)l*DHH*DDIM;
        const __nv_bfloat16* w2h = W2_hi + (size_t)l*DDIM*DHH;
        const __nv_bfloat16* w2l = W2_lo + (size_t)l*DDIM*DHH;

        // qkv = x @ Wqkv + b  (fp32 out for attention)
        run_gemm(xhi, xlo, wqh, wql, bqkv + (size_t)l*NQKV, nullptr,
                 qkv, nullptr, nullptr, MM, NQKV, DDIM, 0);
        attention_kernel<<<dim3(SSEQ/64, BB*HHH), 256, ASMEM>>>(qkv, ohi, olo);
        // h = x + o @ Wo   (fp32 + split)
        run_gemm(ohi, olo, woh, wol, nullptr, x,
                 h, hhi, hlo, MM, DDIM, DDIM, 0);
        // t = gelu(h @ W1 + b1)  (split only)
        run_gemm(hhi, hlo, w1h, w1l, b1 + (size_t)l*DHH, nullptr,
                 nullptr, thi, tlo, MM, DHH, DDIM, 1);
        // x = h + t @ W2 + b2  (fp32 + split)
        run_gemm(thi, tlo, w2h, w2l, b2 + (size_t)l*DDIM, h,
                 x, xhi, xlo, MM, DDIM, DHH, 0);
    }

    // out = x @ Wr + br
    run_gemm(xhi, xlo, Wr_hi, Wr_lo, br, nullptr,
             out, nullptr, nullptr, MM, VVOC, DDIM, 0);
}